// round 1
// baseline (speedup 1.0000x reference)
#include <cuda_runtime.h>
#include <math.h>

#define N_NODES 100000
#define N_EDGES 1600000
#define T_STEPS 8
// gate GEMM: K = 20 (x) + 64 (agg) + 64 (h) = 148, padded to 160

// ---------------- device scratch (no allocations allowed) ----------------
__device__ float g_hbuf[2 * N_NODES * 64];
__device__ float g_c[N_NODES * 64];
__device__ float g_agg[N_NODES * 64];
__device__ float g_gnn[N_NODES * 64];
__device__ float g_xT[T_STEPS * N_NODES * 20];
__device__ float g_W[256 * 160];     // fused, row-permuted gate weights
__device__ float g_bias[256];        // fused, permuted gate bias
__device__ float g_stats[256];       // [0:128) sum, [128:256) sumsq
__device__ float g_scale[128];
__device__ float g_shift[128];
__device__ int   g_deg[N_NODES];
__device__ int   g_offs[N_NODES + 1];
__device__ int   g_cursor[N_NODES];
__device__ int   g_ssrc[N_EDGES];
__device__ float g_h1[N_NODES * 64];
__device__ float g_hidden[N_NODES * 128];
__device__ int   g_is64;

// ---------------- small utility kernels ----------------
__global__ void zero_state() {
    int stride = gridDim.x * blockDim.x;
    int i0 = blockIdx.x * blockDim.x + threadIdx.x;
    for (int k = i0; k < N_NODES * 64; k += stride) {
        g_hbuf[k] = 0.f;
        g_c[k] = 0.f;
        g_agg[k] = 0.f;
    }
    for (int k = i0; k < N_NODES; k += stride) g_deg[k] = 0;
    if (i0 < 256) g_stats[i0] = 0.f;
}

// Detect whether edge_index is int64 (all high words zero) or int32.
__global__ void detect_kernel(const unsigned int* __restrict__ w) {
    __shared__ unsigned int acc;
    if (threadIdx.x == 0) acc = 0u;
    __syncthreads();
    unsigned int v = 0u;
    for (int i = threadIdx.x; i < 2048; i += blockDim.x) v |= w[2 * i + 1];
    atomicOr(&acc, v);
    __syncthreads();
    if (threadIdx.x == 0) g_is64 = (acc == 0u) ? 1 : 0;
}

__device__ __forceinline__ int edge_val(const void* ei, long long idx) {
    if (g_is64) return (int)((const long long*)ei)[idx];
    return ((const int*)ei)[idx];
}

__global__ void hist_kernel(const void* __restrict__ ei) {
    int stride = gridDim.x * blockDim.x;
    for (int e = blockIdx.x * blockDim.x + threadIdx.x; e < N_EDGES; e += stride) {
        int d = edge_val(ei, (long long)N_EDGES + e);
        atomicAdd(&g_deg[d], 1);
    }
}

__global__ void scan_kernel() {
    __shared__ int warpsums[32];
    __shared__ int s_carry;
    int tid = threadIdx.x, lane = tid & 31, wid = tid >> 5;
    if (tid == 0) s_carry = 0;
    __syncthreads();
    for (int base = 0; base < N_NODES; base += 1024) {
        int i = base + tid;
        int v = (i < N_NODES) ? g_deg[i] : 0;
        int x = v;
        #pragma unroll
        for (int off = 1; off < 32; off <<= 1) {
            int y = __shfl_up_sync(0xFFFFFFFFu, x, off);
            if (lane >= off) x += y;
        }
        if (lane == 31) warpsums[wid] = x;
        __syncthreads();
        if (wid == 0) {
            int wv = warpsums[lane];
            #pragma unroll
            for (int off = 1; off < 32; off <<= 1) {
                int y = __shfl_up_sync(0xFFFFFFFFu, wv, off);
                if (lane >= off) wv += y;
            }
            warpsums[lane] = wv;
        }
        __syncthreads();
        int carry = s_carry;
        int woff = (wid == 0) ? 0 : warpsums[wid - 1];
        int excl = x - v + woff + carry;
        if (i < N_NODES) { g_offs[i] = excl; g_cursor[i] = excl; }
        __syncthreads();
        if (tid == 1023) s_carry = carry + warpsums[31];
        __syncthreads();
    }
    if (tid == 0) g_offs[N_NODES] = s_carry;
}

__global__ void scatter_kernel(const void* __restrict__ ei) {
    int stride = gridDim.x * blockDim.x;
    for (int e = blockIdx.x * blockDim.x + threadIdx.x; e < N_EDGES; e += stride) {
        int s = edge_val(ei, e);
        int d = edge_val(ei, (long long)N_EDGES + e);
        int p = atomicAdd(&g_cursor[d], 1);
        g_ssrc[p] = s;
    }
}

// x (N, 30, 8) -> g_xT[t][n][20] (temporal slice transposed)
__global__ void transpose_x(const float* __restrict__ x) {
    int id = blockIdx.x * blockDim.x + threadIdx.x;
    if (id >= N_NODES * T_STEPS) return;
    int t = id & 7;
    int n = id >> 3;
    const float* xr = x + (size_t)n * 240 + 80 + t;
    float* o = g_xT + ((size_t)t * N_NODES + n) * 20;
    #pragma unroll
    for (int j = 0; j < 20; j++) o[j] = xr[j * 8];
}

// Fold GNN projection into gate weights, permute rows to (i,f,g,o) quads.
// permuted row rp: unit u = rp/4, gate q = rp%4, original row r = q*64+u
__global__ void prep_weights(const float* __restrict__ W_ih, const float* __restrict__ W_hh,
                             const float* __restrict__ b_ih, const float* __restrict__ b_hh,
                             const float* __restrict__ W_rel, const float* __restrict__ b_rel,
                             const float* __restrict__ W_root) {
    int rp = blockIdx.x;
    int u = rp >> 2, q = rp & 3;
    int r = q * 64 + u;
    __shared__ float wg[64];
    int tid = threadIdx.x;  // 64 threads
    wg[tid] = W_ih[r * 84 + 20 + tid];
    __syncthreads();
    int c = tid;
    float m1 = 0.f, m2 = 0.f;
    #pragma unroll 8
    for (int j = 0; j < 64; j++) {
        float w = wg[j];
        m1 += w * W_rel[j * 64 + c];
        m2 += w * W_root[j * 64 + c];
    }
    m2 += W_hh[r * 64 + c];
    g_W[rp * 160 + 20 + c] = m1;
    g_W[rp * 160 + 84 + c] = m2;
    if (c < 20) g_W[rp * 160 + c] = W_ih[r * 84 + c];
    if (c < 12) g_W[rp * 160 + 148 + c] = 0.f;
    if (c == 0) {
        float s = b_ih[r] + b_hh[r];
        for (int j = 0; j < 64; j++) s += wg[j] * b_rel[j];
        g_bias[rp] = s;
    }
}

// ---------------- aggregation: warp per dst node ----------------
__global__ void agg_kernel(const float* __restrict__ h) {
    int gw = (blockIdx.x * blockDim.x + threadIdx.x) >> 5;
    int lane = threadIdx.x & 31;
    if (gw >= N_NODES) return;
    int beg = g_offs[gw], end = g_offs[gw + 1];
    float2 acc = make_float2(0.f, 0.f);
    for (int e = beg; e < end; e++) {
        int s = g_ssrc[e];
        float2 v = *reinterpret_cast<const float2*>(h + (size_t)s * 64 + lane * 2);
        acc.x += v.x;
        acc.y += v.y;
    }
    *reinterpret_cast<float2*>(g_agg + (size_t)gw * 64 + lane * 2) = acc;
}

// ---------------- fused gate GEMM + LSTM epilogue ----------------
// gates[N,256] = A[N,160] @ g_W^T ; A = [x_t(20) | agg(64) | h(64) | 0-pad(12)]
// tile 128 nodes x 128 gate-cols, 256 threads, 8x8 per thread
__global__ void __launch_bounds__(256, 2)
gate_kernel(const float* __restrict__ xTt, const float* __restrict__ h_in,
            float* __restrict__ h_out) {
    __shared__ __align__(16) float As[16][132];
    __shared__ __align__(16) float Bs[16][132];
    int tid = threadIdx.x;
    int nodes0 = blockIdx.x * 128;
    int col0 = blockIdx.y * 128;
    int tr = (tid >> 4) * 8;
    int tc = (tid & 15) * 8;
    float acc[8][8];
    #pragma unroll
    for (int i = 0; i < 8; i++)
        #pragma unroll
        for (int j = 0; j < 8; j++) acc[i][j] = 0.f;

    for (int kt = 0; kt < 160; kt += 16) {
        #pragma unroll
        for (int it = 0; it < 8; it++) {
            int idx = tid + it * 256;
            int m = idx >> 4, kk = idx & 15;
            int n = nodes0 + m, gk = kt + kk;
            float v = 0.f;
            if (n < N_NODES) {
                if (gk < 20)       v = xTt[n * 20 + gk];
                else if (gk < 84)  v = g_agg[(size_t)n * 64 + gk - 20];
                else if (gk < 148) v = h_in[(size_t)n * 64 + gk - 84];
            }
            As[kk][m] = v;
        }
        #pragma unroll
        for (int it = 0; it < 8; it++) {
            int idx = tid + it * 256;
            int cc = idx >> 4, kk = idx & 15;
            Bs[kk][cc] = g_W[(col0 + cc) * 160 + kt + kk];
        }
        __syncthreads();
        #pragma unroll
        for (int kk = 0; kk < 16; kk++) {
            float4 a0 = *reinterpret_cast<const float4*>(&As[kk][tr]);
            float4 a1 = *reinterpret_cast<const float4*>(&As[kk][tr + 4]);
            float4 b0 = *reinterpret_cast<const float4*>(&Bs[kk][tc]);
            float4 b1 = *reinterpret_cast<const float4*>(&Bs[kk][tc + 4]);
            float a[8] = {a0.x, a0.y, a0.z, a0.w, a1.x, a1.y, a1.z, a1.w};
            float b[8] = {b0.x, b0.y, b0.z, b0.w, b1.x, b1.y, b1.z, b1.w};
            #pragma unroll
            for (int i = 0; i < 8; i++)
                #pragma unroll
                for (int j = 0; j < 8; j++) acc[i][j] += a[i] * b[j];
        }
        __syncthreads();
    }

    // LSTM epilogue: each 4-col quad = (i,f,g,o) of one hidden unit
    #pragma unroll
    for (int i = 0; i < 8; i++) {
        int n = nodes0 + tr + i;
        if (n >= N_NODES) continue;
        #pragma unroll
        for (int jq = 0; jq < 2; jq++) {
            int jb = jq * 4;
            int gc = col0 + tc + jb;
            int u = gc >> 2;
            float ig = acc[i][jb + 0] + g_bias[gc + 0];
            float fg = acc[i][jb + 1] + g_bias[gc + 1];
            float gg = acc[i][jb + 2] + g_bias[gc + 2];
            float og = acc[i][jb + 3] + g_bias[gc + 3];
            float si = 1.f / (1.f + __expf(-ig));
            float sf = 1.f / (1.f + __expf(-fg));
            float so = 1.f / (1.f + __expf(-og));
            float tg = 2.f / (1.f + __expf(-2.f * gg)) - 1.f;
            size_t ci = (size_t)n * 64 + u;
            float cn = sf * g_c[ci] + si * tg;
            g_c[ci] = cn;
            float tcn = 2.f / (1.f + __expf(-2.f * cn)) - 1.f;
            h_out[ci] = so * tcn;
        }
    }
}

// ---------------- generic small GEMM: out = act(A @ W^T + bias) ----------------
// AMODE 0: A0[n*K+k]
// AMODE 1: k<64 -> A0[n*64+k], else A1[n*64+k-64]
// AMODE 2: like 1 but val = val*g_scale[k] + g_shift[k]   (fused layernorm-over-nodes)
// weights: if Wp1 != null: k<64 -> Wp0[oc*64+k] else Wp1[oc*64+k-64]; else Wp0[oc*K+k]
// EPI 0: bias, EPI 1: bias+relu
template <int AMODE, int EPI>
__global__ void __launch_bounds__(256)
gemm64_kernel(const float* __restrict__ A0, const float* __restrict__ A1,
              const float* __restrict__ Wp0, const float* __restrict__ Wp1,
              const float* __restrict__ bias, float* __restrict__ out,
              int K, int OUT) {
    __shared__ __align__(16) float As[16][68];
    __shared__ __align__(16) float Bs[16][68];
    int tid = threadIdx.x;
    int row0 = blockIdx.x * 64;
    int col0 = blockIdx.y * 64;
    int tr = (tid >> 4) * 4;
    int tc = (tid & 15) * 4;
    float acc[4][4];
    #pragma unroll
    for (int i = 0; i < 4; i++)
        #pragma unroll
        for (int j = 0; j < 4; j++) acc[i][j] = 0.f;

    for (int kt = 0; kt < K; kt += 16) {
        #pragma unroll
        for (int it = 0; it < 4; it++) {
            int idx = tid + it * 256;
            int m = idx >> 4, kk = idx & 15;
            int n = row0 + m, gk = kt + kk;
            float v = 0.f;
            if (n < N_NODES) {
                if (AMODE == 0) {
                    v = A0[(size_t)n * K + gk];
                } else {
                    v = (gk < 64) ? A0[(size_t)n * 64 + gk] : A1[(size_t)n * 64 + gk - 64];
                    if (AMODE == 2) v = v * g_scale[gk] + g_shift[gk];
                }
            }
            As[kk][m] = v;
        }
        #pragma unroll
        for (int it = 0; it < 4; it++) {
            int idx = tid + it * 256;
            int cc = idx >> 4, kk = idx & 15;
            int oc = col0 + cc, gk = kt + kk;
            float w;
            if (Wp1) w = (gk < 64) ? Wp0[oc * 64 + gk] : Wp1[oc * 64 + gk - 64];
            else     w = Wp0[oc * K + gk];
            Bs[kk][cc] = w;
        }
        __syncthreads();
        #pragma unroll
        for (int kk = 0; kk < 16; kk++) {
            float4 a = *reinterpret_cast<const float4*>(&As[kk][tr]);
            float4 b = *reinterpret_cast<const float4*>(&Bs[kk][tc]);
            float av[4] = {a.x, a.y, a.z, a.w};
            float bv[4] = {b.x, b.y, b.z, b.w};
            #pragma unroll
            for (int i = 0; i < 4; i++)
                #pragma unroll
                for (int j = 0; j < 4; j++) acc[i][j] += av[i] * bv[j];
        }
        __syncthreads();
    }
    #pragma unroll
    for (int i = 0; i < 4; i++) {
        int n = row0 + tr + i;
        if (n >= N_NODES) continue;
        #pragma unroll
        for (int j = 0; j < 4; j++) {
            int oc = col0 + tc + j;
            float v = acc[i][j] + bias[oc];
            if (EPI == 1) v = fmaxf(v, 0.f);
            out[(size_t)n * OUT + oc] = v;
        }
    }
}

// ---------------- per-feature stats over nodes ----------------
__global__ void stats_kernel(const float* __restrict__ h, const float* __restrict__ gnn) {
    int c = threadIdx.x & 127;
    int grp = threadIdx.x >> 7;  // 0/1
    int r0 = blockIdx.x * 256;
    int rend = min(r0 + 256, N_NODES);
    float s = 0.f, q = 0.f;
    for (int r = r0 + grp; r < rend; r += 2) {
        float v = (c < 64) ? h[(size_t)r * 64 + c] : gnn[(size_t)r * 64 + c - 64];
        s += v;
        q += v * v;
    }
    atomicAdd(&g_stats[c], s);
    atomicAdd(&g_stats[128 + c], q);
}

__global__ void finalize_stats(const float* __restrict__ gamma, const float* __restrict__ beta) {
    int c = threadIdx.x;
    float mean = g_stats[c] / (float)N_NODES;
    float var = g_stats[128 + c] / (float)N_NODES - mean * mean;
    float rstd = rsqrtf(var + 1e-5f);
    float sc = rstd * gamma[c];
    g_scale[c] = sc;
    g_shift[c] = beta[c] - mean * sc;
}

// ---------------- final projection: out[n] = sigmoid(W_out . hidden[n] + b) ----------------
__global__ void out_kernel(const float* __restrict__ hidden, const float* __restrict__ Wout,
                           const float* __restrict__ bout, float* __restrict__ out) {
    int gw = (blockIdx.x * blockDim.x + threadIdx.x) >> 5;
    int lane = threadIdx.x & 31;
    if (gw >= N_NODES) return;
    const float* hr = hidden + (size_t)gw * 128;
    float s = hr[lane] * Wout[lane] + hr[lane + 32] * Wout[lane + 32] +
              hr[lane + 64] * Wout[lane + 64] + hr[lane + 96] * Wout[lane + 96];
    #pragma unroll
    for (int off = 16; off; off >>= 1) s += __shfl_down_sync(0xFFFFFFFFu, s, off);
    if (lane == 0) out[gw] = 1.f / (1.f + __expf(-(s + bout[0])));
}

// ---------------- launch ----------------
extern "C" void kernel_launch(void* const* d_in, const int* in_sizes, int n_in,
                              void* d_out, int out_size) {
    const float* x      = (const float*)d_in[0];
    const void*  ei     = d_in[1];
    const float* W_ih   = (const float*)d_in[4];
    const float* W_hh   = (const float*)d_in[5];
    const float* b_ih   = (const float*)d_in[6];
    const float* b_hh   = (const float*)d_in[7];
    const float* W_rel  = (const float*)d_in[8];
    const float* b_rel  = (const float*)d_in[9];
    const float* W_root = (const float*)d_in[10];
    const float* gamma  = (const float*)d_in[11];
    const float* beta   = (const float*)d_in[12];
    const float* W1     = (const float*)d_in[13];
    const float* b1     = (const float*)d_in[14];
    const float* W2     = (const float*)d_in[15];
    const float* b2     = (const float*)d_in[16];
    const float* W_out  = (const float*)d_in[17];
    const float* b_out  = (const float*)d_in[18];

    float *hbuf, *agg, *gnn, *h1, *hidden, *xT;
    cudaGetSymbolAddress((void**)&hbuf, g_hbuf);
    cudaGetSymbolAddress((void**)&agg, g_agg);
    cudaGetSymbolAddress((void**)&gnn, g_gnn);
    cudaGetSymbolAddress((void**)&h1, g_h1);
    cudaGetSymbolAddress((void**)&hidden, g_hidden);
    cudaGetSymbolAddress((void**)&xT, g_xT);

    zero_state<<<1024, 256>>>();
    detect_kernel<<<1, 256>>>((const unsigned int*)ei);
    prep_weights<<<256, 64>>>(W_ih, W_hh, b_ih, b_hh, W_rel, b_rel, W_root);
    transpose_x<<<(N_NODES * T_STEPS + 255) / 256, 256>>>(x);
    hist_kernel<<<512, 256>>>(ei);
    scan_kernel<<<1, 1024>>>();
    scatter_kernel<<<512, 256>>>(ei);

    dim3 ggrid((N_NODES + 127) / 128, 2);
    for (int t = 0; t < T_STEPS; t++) {
        const float* h_in = hbuf + (size_t)(t & 1) * N_NODES * 64;
        float* h_out = hbuf + (size_t)((t + 1) & 1) * N_NODES * 64;
        if (t > 0) agg_kernel<<<(N_NODES * 32 + 255) / 256, 256>>>(h_in);
        if (t == T_STEPS - 1) {
            // gnn_out (kept for the head) = agg @ W_rel^T + h @ W_root^T + b_rel
            gemm64_kernel<1, 0><<<dim3((N_NODES + 63) / 64, 1), 256>>>(
                agg, h_in, W_rel, W_root, b_rel, gnn, 128, 64);
        }
        gate_kernel<<<ggrid, 256>>>(xT + (size_t)t * N_NODES * 20, h_in, h_out);
    }
    const float* hfin = hbuf;  // after 8 steps, state is back in buffer 0

    stats_kernel<<<(N_NODES + 255) / 256, 256>>>(hfin, gnn);
    finalize_stats<<<1, 128>>>(gamma, beta);
    gemm64_kernel<2, 1><<<dim3((N_NODES + 63) / 64, 1), 256>>>(
        hfin, gnn, W1, nullptr, b1, h1, 128, 64);
    gemm64_kernel<0, 1><<<dim3((N_NODES + 63) / 64, 2), 256>>>(
        h1, nullptr, W2, nullptr, b2, hidden, 64, 128);
    out_kernel<<<(N_NODES * 32 + 255) / 256, 256>>>(hidden, W_out, b_out, (float*)d_out);
}